// round 15
// baseline (speedup 1.0000x reference)
#include <cuda_runtime.h>
#include <cuda_bf16.h>
#include <cstdint>

#define MAXTOK 16384

// ---------------- scratch (device globals; no allocation allowed) ----------
__device__ __nv_bfloat16 g_fhi[MAXTOK * 96];    // split features [tok][96]
__device__ __nv_bfloat16 g_flo[MAXTOK * 96];
__device__ __nv_bfloat16 g_h1hi[MAXTOK * 256];  // sorted order, split bf16
__device__ __nv_bfloat16 g_h1lo[MAXTOK * 256];
__device__ __nv_bfloat16 g_Whi[65536];  // W2 [j][k256]; W3,W4 [j][k128]
__device__ __nv_bfloat16 g_Wlo[65536];
__device__ __nv_bfloat16 g_W1hi[491520];  // [type][j(256)][k(96)]
__device__ __nv_bfloat16 g_W1lo[491520];
__device__ float g_E1[20 * 256];
__device__ float g_C1[10 * 256];
__device__ int g_hist[20];
__device__ int g_base[20];
__device__ int g_cursor[20];
__device__ int g_order[MAXTOK];         // sorted pos -> original token
__device__ int g_done;

static __device__ __forceinline__ uint32_t smem_u32(const void* p) {
    uint32_t a;
    asm("{ .reg .u64 t; cvta.to.shared.u64 t, %1; cvt.u32.u64 %0, t; }" : "=r"(a) : "l"(p));
    return a;
}
static __device__ __forceinline__ void splitg(__nv_bfloat16* hi, __nv_bfloat16* lo,
                                              size_t idx, float v) {
    __nv_bfloat16 h = __float2bfloat16(v);
    hi[idx] = h;
    lo[idx] = __float2bfloat16(v - __bfloat162float(h));
}

// ---------------- setup: tables + weight splits + split features ------------
__global__ void __launch_bounds__(256)
k_setup(const float* __restrict__ aa_emb, const float* __restrict__ ch_emb,
        const float* __restrict__ W1, const float* __restrict__ b1,
        const float* __restrict__ W2, const float* __restrict__ W3,
        const float* __restrict__ W4,
        const float* __restrict__ xyz, const float* __restrict__ ori,
        const float* __restrict__ dih, const int* __restrict__ seq,
        int ntok, int nfeatblk) {
    int b = blockIdx.x, tid = threadIdx.x;
    if (b < 30) {   // E1 / C1 tables
        int j = tid;
        if (b < 20) {
            float acc = b1[j];
#pragma unroll 8
            for (int k = 0; k < 128; k++) acc += aa_emb[b * 128 + k] * W1[k * 256 + j];
            g_E1[b * 256 + j] = acc;
        } else {
            int c = b - 20;
            float acc = 0.f;
            if (c != 0) {
#pragma unroll 8
                for (int k = 0; k < 128; k++)
                    acc += ch_emb[c * 128 + k] * W1[(1067 + k) * 256 + j];
            }
            g_C1[c * 256 + j] = acc;
        }
        return;
    }
    if (b < 62) {   // split W2/W3/W4 into bf16 hi/lo, B-tile layout [j][k]
        int w = b - 30;
#pragma unroll
        for (int i = 0; i < 8; i++) {
            int idx = w * 2048 + tid + 256 * i;
            float v;
            if (idx < 32768) {
                int j = idx >> 8, k = idx & 255;
                v = W2[(size_t)k * 128 + j];
            } else if (idx < 49152) {
                int r = idx - 32768, j = r >> 7, k = r & 127;
                v = W3[(size_t)k * 128 + j];
            } else {
                int r = idx - 49152, j = r >> 7, k = r & 127;
                v = W4[(size_t)k * 128 + j];
            }
            splitg(g_Whi, g_Wlo, idx, v);
        }
        return;
    }
    if (b < 302) {  // split W1 per-type tiles: [s][j][96], k>=84 zero
        int w = b - 62;
#pragma unroll
        for (int i = 0; i < 8; i++) {
            int idx = w * 2048 + i * 256 + tid;
            int s = idx / 24576, r = idx % 24576;
            int j = r / 96, k = r % 96;
            float v = 0.f;
            if (k < 45)      v = W1[(size_t)(128 + s * 45 + k) * 256 + j];
            else if (k < 84) v = W1[(size_t)(1028 + k - 45) * 256 + j];
            splitg(g_W1hi, g_W1lo, idx, v);
        }
        return;
    }
    int t = (b - 302) * 256 + tid;
    if (t < ntok) {
        const float* X = xyz + t * 45;
        float ca0 = X[3], ca1 = X[4], ca2 = X[5];   // CA_IDX = 1
        float o[9];
#pragma unroll
        for (int i = 0; i < 9; i++) o[i] = ori[t * 9 + i];
        size_t fb0 = (size_t)t * 96;
#pragma unroll
        for (int a = 0; a < 15; a++) {
            float rx = X[a * 3 + 0] - ca0;
            float ry = X[a * 3 + 1] - ca1;
            float rz = X[a * 3 + 2] - ca2;
#pragma unroll
            for (int i = 0; i < 3; i++)
                splitg(g_fhi, g_flo, fb0 + a * 3 + i,
                       o[i] * rx + o[3 + i] * ry + o[6 + i] * rz);
        }
        const float fb[6] = {1.f, 2.f, 3.f, 1.f, 0.5f, 1.f / 3.f};
#pragma unroll
        for (int d = 0; d < 3; d++) {
            float x = dih[t * 3 + d];
            int bo = 45 + d * 13;
            splitg(g_fhi, g_flo, fb0 + bo, x);
#pragma unroll
            for (int u = 0; u < 6; u++) {
                splitg(g_fhi, g_flo, fb0 + bo + 1 + u, sinf(fb[u] * x));
                splitg(g_fhi, g_flo, fb0 + bo + 7 + u, cosf(fb[u] * x));
            }
        }
#pragma unroll
        for (int i = 84; i < 96; i++) {
            g_fhi[fb0 + i] = __float2bfloat16(0.f);
            g_flo[fb0 + i] = __float2bfloat16(0.f);
        }
        atomicAdd(&g_hist[seq[t]], 1);
    }
    __syncthreads();
    if (tid == 0) {
        __threadfence();
        if (atomicAdd(&g_done, 1) == nfeatblk - 1) {
            __threadfence();
            int s = 0;
            for (int i = 0; i < 20; i++) {
                int h = atomicAdd(&g_hist[i], 0);
                g_base[i] = s; s += h;
            }
            atomicExch(&g_done, 0);
        }
    }
}

// ---------------- block-aggregated counting-sort scatter ---------------------
__global__ void __launch_bounds__(256)
k_scatter(const int* __restrict__ seq, int ntok) {
    __shared__ int lh[20], lb[20], lc[20];
    int tid = threadIdx.x;
    if (tid < 20) { lh[tid] = 0; lc[tid] = 0; }
    __syncthreads();
    int t = blockIdx.x * 256 + tid;
    int s = -1;
    if (t < ntok) { s = seq[t]; atomicAdd(&lh[s], 1); }
    __syncthreads();
    if (tid < 20 && lh[tid] > 0) lb[tid] = atomicAdd(&g_cursor[tid], lh[tid]);
    __syncthreads();
    if (t < ntok) {
        int p = atomicAdd(&lc[s], 1);
        g_order[g_base[s] + lb[s] + p] = t;
    }
}

// ============================================================================
// Shared mma machinery (validated R11-R14)
// ============================================================================
#define SMSTRIDE 136

#define LDSM_X4(r0, r1, r2, r3, addr) \
    asm volatile("ldmatrix.sync.aligned.m8n8.x4.shared.b16 {%0,%1,%2,%3}, [%4];" \
        : "=r"(r0), "=r"(r1), "=r"(r2), "=r"(r3) : "r"(addr))

static __device__ __forceinline__ void mma16816(float* c, const uint32_t* a,
                                                const uint32_t* b) {
    asm volatile(
        "mma.sync.aligned.m16n8k16.row.col.f32.bf16.bf16.f32 "
        "{%0,%1,%2,%3}, {%4,%5,%6,%7}, {%8,%9}, {%0,%1,%2,%3};"
        : "+f"(c[0]), "+f"(c[1]), "+f"(c[2]), "+f"(c[3])
        : "r"(a[0]), "r"(a[1]), "r"(a[2]), "r"(a[3]), "r"(b[0]), "r"(b[1]));
}

static __device__ __forceinline__ void split_pair(__nv_bfloat16* hiA,
                                                  __nv_bfloat16* loA,
                                                  int r, int col,
                                                  float v0, float v1) {
    __nv_bfloat16 h0 = __float2bfloat16(v0), h1 = __float2bfloat16(v1);
    __nv_bfloat16 l0 = __float2bfloat16(v0 - __bfloat162float(h0));
    __nv_bfloat16 l1 = __float2bfloat16(v1 - __bfloat162float(h1));
    __nv_bfloat162 hp, lp;
    hp.x = h0; hp.y = h1; lp.x = l0; lp.y = l1;
    *(__nv_bfloat162*)&hiA[r * SMSTRIDE + col] = hp;
    *(__nv_bfloat162*)&loA[r * SMSTRIDE + col] = lp;
}

template <int KSTEPS>
static __device__ __forceinline__ void mma_loop(uint32_t aHi, uint32_t aLo,
                                                uint32_t bHi, uint32_t bLo,
                                                int m0, int n0, int lane,
                                                float c[2][4][4]) {
    int arow = lane & 15, akhalf = (lane >> 4) << 3;
    int bn = ((lane >> 4) << 3) + (lane & 7), bkhalf = ((lane >> 3) & 1) << 3;
#pragma unroll
    for (int ks = 0; ks < KSTEPS; ks++) {
        int k0 = ks * 16;
        uint32_t ah[2][4], al[2][4], bh[4][2], bl[4][2];
#pragma unroll
        for (int mt = 0; mt < 2; mt++) {
            uint32_t off =
                (uint32_t)(((m0 + mt * 16 + arow) * SMSTRIDE + k0 + akhalf) * 2);
            LDSM_X4(ah[mt][0], ah[mt][1], ah[mt][2], ah[mt][3], aHi + off);
            LDSM_X4(al[mt][0], al[mt][1], al[mt][2], al[mt][3], aLo + off);
        }
#pragma unroll
        for (int ng = 0; ng < 2; ng++) {
            uint32_t off =
                (uint32_t)(((n0 + ng * 16 + bn) * SMSTRIDE + k0 + bkhalf) * 2);
            uint32_t r0, r1, r2, r3;
            LDSM_X4(r0, r1, r2, r3, bHi + off);
            bh[ng * 2][0] = r0;     bh[ng * 2][1] = r1;
            bh[ng * 2 + 1][0] = r2; bh[ng * 2 + 1][1] = r3;
            LDSM_X4(r0, r1, r2, r3, bLo + off);
            bl[ng * 2][0] = r0;     bl[ng * 2][1] = r1;
            bl[ng * 2 + 1][0] = r2; bl[ng * 2 + 1][1] = r3;
        }
#pragma unroll
        for (int mt = 0; mt < 2; mt++)
#pragma unroll
            for (int nt = 0; nt < 4; nt++) {
                mma16816(c[mt][nt], ah[mt], bh[nt]);
                mma16816(c[mt][nt], ah[mt], bl[nt]);
                mma16816(c[mt][nt], al[mt], bh[nt]);
            }
    }
}

// ============================================================================
// Layer 1 via HMMA: grid (20 types, 2 j-halves, 14 slices), 256 thr, 2 blk/SM.
// M=64 tokens x N=128 j x K=96 (84 + zero pad). Epilogue adds E1+C1, relu,
// split-stores h1 in sorted order.
// ============================================================================
#define L1_TA 17408                    // 64*136*2
#define L1_TB 34816                    // 128*136*2
#define L1_ALO (L1_TA)
#define L1_BHI (L1_TA * 2)
#define L1_BLO (L1_TA * 2 + L1_TB)
#define L1_E1S (L1_TA * 2 + L1_TB * 2) // 104448
#define L1_C1S (L1_E1S + 512)
#define L1_CS  (L1_C1S + 5120)         // 110080
#define SMEM_L1_BYTES (L1_CS + 256)    // 110336

__global__ void __launch_bounds__(256, 2)
k_l1t(const int* __restrict__ cidx) {
    extern __shared__ __align__(16) char smem[];
    __nv_bfloat16* Ahi = (__nv_bfloat16*)(smem);
    __nv_bfloat16* Alo = (__nv_bfloat16*)(smem + L1_ALO);
    __nv_bfloat16* Bhi = (__nv_bfloat16*)(smem + L1_BHI);
    __nv_bfloat16* Blo = (__nv_bfloat16*)(smem + L1_BLO);
    float* E1s = (float*)(smem + L1_E1S);
    float* C1s = (float*)(smem + L1_C1S);
    int*   cs  = (int*)(smem + L1_CS);
    uint32_t aHi = smem_u32(Ahi), aLo = smem_u32(Alo);
    uint32_t bHi = smem_u32(Bhi), bLo = smem_u32(Blo);

    int tid = threadIdx.x, wid = tid >> 5, lane = tid & 31;
    int m0 = (wid >> 2) * 32, n0 = (wid & 3) * 32;
    int s = blockIdx.x, jh = blockIdx.y;
    if (s == 0 && jh == 0 && blockIdx.z == 0 && tid < 20) g_cursor[tid] = 0;

    if (tid < 128) E1s[tid] = g_E1[s * 256 + jh * 128 + tid];
    for (int i = tid; i < 1280; i += 256)
        C1s[i] = g_C1[(i >> 7) * 256 + jh * 128 + (i & 127)];
    // B: per-type W1 split tile, rows j = jh*128 .. +127, 96 k cols (12 uint4)
    for (int p = tid; p < 1536; p += 256) {
        int j = p / 12, sg = (p % 12) * 8;
        size_t src = (size_t)s * 24576 + (size_t)(jh * 128 + j) * 96 + sg;
        *(uint4*)&Bhi[j * SMSTRIDE + sg] = *(const uint4*)&g_W1hi[src];
        *(uint4*)&Blo[j * SMSTRIDE + sg] = *(const uint4*)&g_W1lo[src];
    }

    int cnt = g_hist[s], base = g_base[s];
    int st = cnt * blockIdx.z / 14, en = cnt * (blockIdx.z + 1) / 14;

    for (int g0 = st; g0 < en; g0 += 64) {
        int n = min(64, en - g0);
        __syncthreads();   // prev group's A/cs readers done (also orders B/E1/C1 1st iter)
        if (tid < 64) cs[tid] = (tid < n) ? cidx[g_order[base + g0 + tid]] : 0;
        for (int p = tid; p < 768; p += 256) {
            int row = p / 12, sg = (p % 12) * 8;
            uint4 vh = make_uint4(0, 0, 0, 0), vl = vh;
            if (row < n) {
                size_t src = (size_t)g_order[base + g0 + row] * 96 + sg;
                vh = *(const uint4*)&g_fhi[src];
                vl = *(const uint4*)&g_flo[src];
            }
            *(uint4*)&Ahi[row * SMSTRIDE + sg] = vh;
            *(uint4*)&Alo[row * SMSTRIDE + sg] = vl;
        }
        __syncthreads();
        float c[2][4][4];
#pragma unroll
        for (int mt = 0; mt < 2; mt++)
#pragma unroll
            for (int nt = 0; nt < 4; nt++)
#pragma unroll
                for (int i = 0; i < 4; i++) c[mt][nt][i] = 0.f;
        mma_loop<6>(aHi, aLo, bHi, bLo, m0, n0, lane, c);
        // epilogue: + E1 + C1, relu, split-store h1 (sorted order)
#pragma unroll
        for (int mt = 0; mt < 2; mt++)
#pragma unroll
            for (int nt = 0; nt < 4; nt++) {
                int col = n0 + nt * 8 + (lane & 3) * 2;
                int r = m0 + mt * 16 + (lane >> 2);
                float e0 = E1s[col], e1 = E1s[col + 1];
#pragma unroll
                for (int h = 0; h < 2; h++) {
                    int rr = r + 8 * h;
                    if (rr < n) {
                        int cc = cs[rr];
                        float v0 = fmaxf(c[mt][nt][2 * h + 0] + e0 +
                                         C1s[cc * 128 + col], 0.f);
                        float v1 = fmaxf(c[mt][nt][2 * h + 1] + e1 +
                                         C1s[cc * 128 + col + 1], 0.f);
                        size_t d = (size_t)(base + g0 + rr) * 256 + jh * 128 + col;
                        __nv_bfloat16 h0 = __float2bfloat16(v0);
                        __nv_bfloat16 h1 = __float2bfloat16(v1);
                        __nv_bfloat162 hp, lp;
                        hp.x = h0; hp.y = h1;
                        lp.x = __float2bfloat16(v0 - __bfloat162float(h0));
                        lp.y = __float2bfloat16(v1 - __bfloat162float(h1));
                        *(__nv_bfloat162*)&g_h1hi[d] = hp;
                        *(__nv_bfloat162*)&g_h1lo[d] = lp;
                    }
                }
            }
    }
}

// ============================================================================
// Fused MLP (layers 2,3,4) — unchanged from R14 (passing, 30.2 us)
// ============================================================================
#define TILE_A 17408
#define TILE_B 34816
#define OFF_ALO (TILE_A)
#define OFF_BHI (TILE_A * 2)
#define OFF_BLO (TILE_A * 2 + TILE_B)
#define OFF_B2S (TILE_A * 2 + TILE_B * 2)   // 104448
#define OFF_B3S (OFF_B2S + 512)
#define OFF_B4S (OFF_B3S + 512)
#define OFF_OSX (OFF_B4S + 512)
#define SMEM_MLP_BYTES (OFF_OSX + 256)      // 106240

__global__ void __launch_bounds__(256, 2)
k_mlp(const float* __restrict__ b2, const float* __restrict__ b3,
      const float* __restrict__ b4, float* __restrict__ out, int ntok) {
    extern __shared__ __align__(16) char smem[];
    __nv_bfloat16* Ahi = (__nv_bfloat16*)(smem);
    __nv_bfloat16* Alo = (__nv_bfloat16*)(smem + OFF_ALO);
    __nv_bfloat16* Bhi = (__nv_bfloat16*)(smem + OFF_BHI);
    __nv_bfloat16* Blo = (__nv_bfloat16*)(smem + OFF_BLO);
    float* b2s = (float*)(smem + OFF_B2S);
    float* b3s = (float*)(smem + OFF_B3S);
    float* b4s = (float*)(smem + OFF_B4S);
    int*   os  = (int*)(smem + OFF_OSX);
    uint32_t aHi = smem_u32(Ahi), aLo = smem_u32(Alo);
    uint32_t bHi = smem_u32(Bhi), bLo = smem_u32(Blo);

    int tid = threadIdx.x, wid = tid >> 5, lane = tid & 31;
    int m0 = (wid >> 2) * 32, n0 = (wid & 3) * 32;
    int t0 = blockIdx.x * 64;
    if (blockIdx.x == 0 && tid < 20) g_hist[tid] = 0;   // reset for next replay
    if (tid < 128) { b2s[tid] = b2[tid]; b3s[tid] = b3[tid]; b4s[tid] = b4[tid]; }
    if (tid < 64) os[tid] = (t0 + tid < ntok) ? g_order[t0 + tid] : 0;

    float c[2][4][4];
#pragma unroll
    for (int mt = 0; mt < 2; mt++)
#pragma unroll
        for (int nt = 0; nt < 4; nt++)
#pragma unroll
            for (int i = 0; i < 4; i++) c[mt][nt][i] = 0.f;

    for (int ch = 0; ch < 2; ch++) {
        if (ch) __syncthreads();
        for (int p = tid; p < 1024; p += 256) {
            int row = p >> 4, sg = (p & 15) * 8;
            int gt = t0 + row;
            uint4 vh = make_uint4(0, 0, 0, 0), vl = vh;
            if (gt < ntok) {
                size_t src = (size_t)gt * 256 + ch * 128 + sg;
                vh = *(const uint4*)&g_h1hi[src];
                vl = *(const uint4*)&g_h1lo[src];
            }
            *(uint4*)&Ahi[row * SMSTRIDE + sg] = vh;
            *(uint4*)&Alo[row * SMSTRIDE + sg] = vl;
        }
        for (int p = tid; p < 2048; p += 256) {
            int j = p >> 4, sg = (p & 15) * 8;
            size_t src = (size_t)j * 256 + ch * 128 + sg;
            *(uint4*)&Bhi[j * SMSTRIDE + sg] = *(const uint4*)&g_Whi[src];
            *(uint4*)&Blo[j * SMSTRIDE + sg] = *(const uint4*)&g_Wlo[src];
        }
        __syncthreads();
        mma_loop<8>(aHi, aLo, bHi, bLo, m0, n0, lane, c);
    }

#pragma unroll 1
    for (int layer = 0; layer < 2; layer++) {
        size_t wbase = (layer == 0) ? 32768 : 49152;
        const float* bs = (layer == 0) ? b2s : b3s;
        __syncthreads();
#pragma unroll
        for (int mt = 0; mt < 2; mt++)
#pragma unroll
            for (int nt = 0; nt < 4; nt++) {
                int col = n0 + nt * 8 + (lane & 3) * 2;
                int r = m0 + mt * 16 + (lane >> 2);
                float bv0 = bs[col], bv1 = bs[col + 1];
                split_pair(Ahi, Alo, r, col,
                           fmaxf(c[mt][nt][0] + bv0, 0.f),
                           fmaxf(c[mt][nt][1] + bv1, 0.f));
                split_pair(Ahi, Alo, r + 8, col,
                           fmaxf(c[mt][nt][2] + bv0, 0.f),
                           fmaxf(c[mt][nt][3] + bv1, 0.f));
#pragma unroll
                for (int i = 0; i < 4; i++) c[mt][nt][i] = 0.f;
            }
        for (int p = tid; p < 2048; p += 256) {
            int j = p >> 4, sg = (p & 15) * 8;
            size_t src = wbase + (size_t)j * 128 + sg;
            *(uint4*)&Bhi[j * SMSTRIDE + sg] = *(const uint4*)&g_Whi[src];
            *(uint4*)&Blo[j * SMSTRIDE + sg] = *(const uint4*)&g_Wlo[src];
        }
        __syncthreads();
        mma_loop<8>(aHi, aLo, bHi, bLo, m0, n0, lane, c);
    }

#pragma unroll
    for (int mt = 0; mt < 2; mt++)
#pragma unroll
        for (int nt = 0; nt < 4; nt++) {
            int col = n0 + nt * 8 + (lane & 3) * 2;
            int r = m0 + mt * 16 + (lane >> 2);
            float bv0 = b4s[col], bv1 = b4s[col + 1];
            if (t0 + r < ntok) {
                float2 v = make_float2(c[mt][nt][0] + bv0, c[mt][nt][1] + bv1);
                *(float2*)&out[(size_t)os[r] * 128 + col] = v;
            }
            if (t0 + r + 8 < ntok) {
                float2 v = make_float2(c[mt][nt][2] + bv0, c[mt][nt][3] + bv1);
                *(float2*)&out[(size_t)os[r + 8] * 128 + col] = v;
            }
        }
}

// ---------------- launch ----------------------------------------------------
extern "C" void kernel_launch(void* const* d_in, const int* in_sizes, int n_in,
                              void* d_out, int out_size) {
    const int*   seq    = (const int*)  d_in[0];
    const float* xyz    = (const float*)d_in[1];
    const float* dih    = (const float*)d_in[2];
    const int*   cidx   = (const int*)  d_in[3];
    const float* ori    = (const float*)d_in[4];
    /* d_in[5] = atom_mask : unused by reference */
    const float* aa_emb = (const float*)d_in[6];
    const float* ch_emb = (const float*)d_in[7];
    const float* W1 = (const float*)d_in[8];
    const float* b1 = (const float*)d_in[9];
    const float* W2 = (const float*)d_in[10];
    const float* b2 = (const float*)d_in[11];
    const float* W3 = (const float*)d_in[12];
    const float* b3 = (const float*)d_in[13];
    const float* W4 = (const float*)d_in[14];
    const float* b4 = (const float*)d_in[15];
    float* out = (float*)d_out;
    int ntok = in_sizes[0];
    if (ntok > MAXTOK) ntok = MAXTOK;

    int nfeatblk = (ntok + 255) / 256;
    int nblk64 = (ntok + 63) / 64;
    cudaFuncSetAttribute(k_l1t, cudaFuncAttributeMaxDynamicSharedMemorySize,
                         SMEM_L1_BYTES);
    cudaFuncSetAttribute(k_mlp, cudaFuncAttributeMaxDynamicSharedMemorySize,
                         SMEM_MLP_BYTES);

    k_setup<<<302 + nfeatblk, 256>>>(aa_emb, ch_emb, W1, b1, W2, W3, W4,
                                     xyz, ori, dih, seq, ntok, nfeatblk);
    k_scatter<<<(ntok + 255) / 256, 256>>>(seq, ntok);
    k_l1t<<<dim3(20, 2, 14), 256, SMEM_L1_BYTES>>>(cidx);
    k_mlp<<<nblk64, 256, SMEM_MLP_BYTES>>>(b2, b3, b4, out, ntok);
}

// round 16
// speedup vs baseline: 1.4983x; 1.4983x over previous
#include <cuda_runtime.h>
#include <cuda_bf16.h>
#include <cstdint>

#define MAXTOK 16384

// ---------------- scratch (device globals; no allocation allowed) ----------
__device__ float g_feat[MAXTOK * 88];   // [tok][88]: 0..44 coord, 45..83 dihedral
__device__ __nv_bfloat16 g_h1hi[MAXTOK * 256];  // sorted order, split bf16
__device__ __nv_bfloat16 g_h1lo[MAXTOK * 256];
__device__ __nv_bfloat16 g_Whi[65536];  // W2 [j][k256]; W3,W4 [j][k128]
__device__ __nv_bfloat16 g_Wlo[65536];
__device__ float g_E1[20 * 256];
__device__ float g_C1[10 * 256];
__device__ int g_hist[20];
__device__ int g_base[20];
__device__ int g_cursor[20];
__device__ int g_order[MAXTOK];         // sorted pos -> original token
__device__ int g_done;

typedef unsigned long long ull;

static __device__ __forceinline__ ull f2pack(float lo, float hi) {
    ull r; asm("mov.b64 %0,{%1,%2};" : "=l"(r) : "f"(lo), "f"(hi)); return r;
}
static __device__ __forceinline__ void f2unpack(ull v, float& lo, float& hi) {
    asm("mov.b64 {%0,%1},%2;" : "=f"(lo), "=f"(hi) : "l"(v));
}
static __device__ __forceinline__ ull ffma2(ull a, ull b, ull c) {
    ull d; asm("fma.rn.f32x2 %0,%1,%2,%3;" : "=l"(d) : "l"(a), "l"(b), "l"(c)); return d;
}
static __device__ __forceinline__ ull fadd2(ull a, ull b) {
    ull d; asm("add.rn.f32x2 %0,%1,%2;" : "=l"(d) : "l"(a), "l"(b)); return d;
}
static __device__ __forceinline__ uint32_t smem_u32(const void* p) {
    uint32_t a;
    asm("{ .reg .u64 t; cvta.to.shared.u64 t, %1; cvt.u32.u64 %0, t; }" : "=r"(a) : "l"(p));
    return a;
}

// ---------------- setup: tables + weight split + features + hist + scan -----
__global__ void __launch_bounds__(256)
k_setup(const float* __restrict__ aa_emb, const float* __restrict__ ch_emb,
        const float* __restrict__ W1, const float* __restrict__ b1,
        const float* __restrict__ W2, const float* __restrict__ W3,
        const float* __restrict__ W4,
        const float* __restrict__ xyz, const float* __restrict__ ori,
        const float* __restrict__ dih, const int* __restrict__ seq,
        int ntok, int nfeatblk) {
    int b = blockIdx.x, tid = threadIdx.x;
    if (b < 30) {
        int j = tid;
        if (b < 20) {
            float acc = b1[j];
#pragma unroll 8
            for (int k = 0; k < 128; k++) acc += aa_emb[b * 128 + k] * W1[k * 256 + j];
            g_E1[b * 256 + j] = acc;
        } else {
            int c = b - 20;
            float acc = 0.f;
            if (c != 0) {
#pragma unroll 8
                for (int k = 0; k < 128; k++)
                    acc += ch_emb[c * 128 + k] * W1[(1067 + k) * 256 + j];
            }
            g_C1[c * 256 + j] = acc;
        }
        return;
    }
    if (b < 62) {   // split W2/W3/W4 into bf16 hi/lo, B-tile layout [j][k]
        int w = b - 30;
#pragma unroll
        for (int i = 0; i < 8; i++) {
            int idx = w * 2048 + tid + 256 * i;
            float v;
            if (idx < 32768) {
                int j = idx >> 8, k = idx & 255;
                v = W2[(size_t)k * 128 + j];
            } else if (idx < 49152) {
                int r = idx - 32768, j = r >> 7, k = r & 127;
                v = W3[(size_t)k * 128 + j];
            } else {
                int r = idx - 49152, j = r >> 7, k = r & 127;
                v = W4[(size_t)k * 128 + j];
            }
            __nv_bfloat16 h = __float2bfloat16(v);
            g_Whi[idx] = h;
            g_Wlo[idx] = __float2bfloat16(v - __bfloat162float(h));
        }
        return;
    }
    int t = (b - 62) * 256 + tid;
    if (t < ntok) {
        const float* X = xyz + t * 45;
        float ca0 = X[3], ca1 = X[4], ca2 = X[5];   // CA_IDX = 1
        float o[9];
#pragma unroll
        for (int i = 0; i < 9; i++) o[i] = ori[t * 9 + i];
        float F[88];
#pragma unroll
        for (int a = 0; a < 15; a++) {
            float rx = X[a * 3 + 0] - ca0;
            float ry = X[a * 3 + 1] - ca1;
            float rz = X[a * 3 + 2] - ca2;
#pragma unroll
            for (int i = 0; i < 3; i++)
                F[a * 3 + i] = o[i] * rx + o[3 + i] * ry + o[6 + i] * rz;
        }
        const float fb[6] = {1.f, 2.f, 3.f, 1.f, 0.5f, 1.f / 3.f};
#pragma unroll
        for (int d = 0; d < 3; d++) {
            float x = dih[t * 3 + d];
            int bo = 45 + d * 13;
            F[bo] = x;
#pragma unroll
            for (int u = 0; u < 6; u++) {
                F[bo + 1 + u] = sinf(fb[u] * x);
                F[bo + 7 + u] = cosf(fb[u] * x);
            }
        }
        F[84] = 0.f; F[85] = 0.f; F[86] = 0.f; F[87] = 0.f;
        float* dst = g_feat + (size_t)t * 88;
#pragma unroll
        for (int i = 0; i < 22; i++)
            *(float4*)&dst[i * 4] = *(const float4*)&F[i * 4];
        atomicAdd(&g_hist[seq[t]], 1);
    }
    __syncthreads();
    if (tid == 0) {
        __threadfence();
        if (atomicAdd(&g_done, 1) == nfeatblk - 1) {
            __threadfence();
            int s = 0;
            for (int i = 0; i < 20; i++) {
                int h = atomicAdd(&g_hist[i], 0);
                g_base[i] = s; s += h;
            }
            atomicExch(&g_done, 0);
        }
    }
}

// ---------------- block-aggregated counting-sort scatter ---------------------
__global__ void __launch_bounds__(256)
k_scatter(const int* __restrict__ seq, int ntok) {
    __shared__ int lh[20], lb[20], lc[20];
    int tid = threadIdx.x;
    if (tid < 20) { lh[tid] = 0; lc[tid] = 0; }
    __syncthreads();
    int t = blockIdx.x * 256 + tid;
    int s = -1;
    if (t < ntok) { s = seq[t]; atomicAdd(&lh[s], 1); }
    __syncthreads();
    if (tid < 20 && lh[tid] > 0) lb[tid] = atomicAdd(&g_cursor[tid], lh[tid]);
    __syncthreads();
    if (t < ntok) {
        int p = atomicAdd(&lc[s], 1);
        g_order[g_base[s] + lb[s] + p] = t;
    }
}

// ---------------- layer 1 (scalar FFMA2), W tile persistent per block --------
// grid (20, 7); 512 thr; 2 blocks/SM; 32 tokens/group, ~4 groups/block.
__global__ void __launch_bounds__(512, 2)
k_l1(const float* __restrict__ W1, const int* __restrict__ cidx) {
    extern __shared__ __align__(16) float sm[];
    float* Ws  = sm;            // 84*256 = 21504 (persistent)
    float* C1s = sm + 21504;    // 2560
    float* E1s = sm + 24064;    // 256
    float* xs  = sm + 24320;    // 84*36 = 3024
    int*   cs  = (int*)(sm + 27344);  // 32 ints
    int tid = threadIdx.x, s = blockIdx.x;
    if (s == 0 && blockIdx.y == 0 && tid < 20) g_cursor[tid] = 0;
    // stage W tile ONCE (84 rows x 256)
    for (int i = tid * 4; i < 21504; i += 2048) {
        int r = i >> 8, c = i & 255;
        int src = (r < 45) ? (128 + s * 45 + r) : (1028 + r - 45);
        *(float4*)&Ws[i] = *(const float4*)&W1[src * 256 + c];
    }
    for (int i = tid; i < 2560; i += 512) C1s[i] = g_C1[i];
    if (tid < 256) E1s[tid] = g_E1[s * 256 + tid];

    int cnt = g_hist[s], base = g_base[s];
    int st = cnt * blockIdx.y / 7, en = cnt * (blockIdx.y + 1) / 7;
    int lane = tid & 31, w_ = tid >> 5;
    int jq = w_ & 3, th = w_ >> 2;
    int j0 = jq * 64 + lane, j1 = j0 + 32, T0 = th * 8;
    __syncthreads();
    ull e0 = f2pack(E1s[j0], E1s[j0]);
    ull e1 = f2pack(E1s[j1], E1s[j1]);

    for (int g0 = st; g0 < en; g0 += 32) {
        int n = min(32, en - g0);
        __syncthreads();   // prev group's xs/cs readers done
        if (tid < 32) cs[tid] = (tid < n) ? cidx[g_order[base + g0 + tid]] : 0;
        for (int it = w_; it < 24; it += 16) {
            int kc = it % 3, tc = it / 3;
            int k = kc * 32 + lane;
            if (k < 84) {
                int tb = tc * 4;
                float v[4];
#pragma unroll
                for (int i = 0; i < 4; i++) {
                    int t = tb + i;
                    v[i] = (t < n) ? g_feat[(size_t)g_order[base + g0 + t] * 88 + k] : 0.f;
                }
                *(float4*)&xs[k * 36 + tb] = make_float4(v[0], v[1], v[2], v[3]);
            }
        }
        __syncthreads();
        ull a0[4], a1[4];
#pragma unroll
        for (int u = 0; u < 4; u++) {
            int ca = cs[T0 + 2 * u], cb = cs[T0 + 2 * u + 1];
            a0[u] = fadd2(e0, f2pack(C1s[ca * 256 + j0], C1s[cb * 256 + j0]));
            a1[u] = fadd2(e1, f2pack(C1s[ca * 256 + j1], C1s[cb * 256 + j1]));
        }
#pragma unroll 4
        for (int k = 0; k < 84; k++) {
            float w0 = Ws[k * 256 + j0], w1 = Ws[k * 256 + j1];
            ull wd0 = f2pack(w0, w0), wd1 = f2pack(w1, w1);
            const ulonglong2* xr = (const ulonglong2*)&xs[k * 36 + T0];
            ulonglong2 xa = xr[0], xb = xr[1];
            a0[0] = ffma2(xa.x, wd0, a0[0]); a1[0] = ffma2(xa.x, wd1, a1[0]);
            a0[1] = ffma2(xa.y, wd0, a0[1]); a1[1] = ffma2(xa.y, wd1, a1[1]);
            a0[2] = ffma2(xb.x, wd0, a0[2]); a1[2] = ffma2(xb.x, wd1, a1[2]);
            a0[3] = ffma2(xb.y, wd0, a0[3]); a1[3] = ffma2(xb.y, wd1, a1[3]);
        }
#pragma unroll
        for (int u = 0; u < 4; u++) {
            int ta = T0 + 2 * u;
            if (ta < n) {
                int pa = (base + g0 + ta) * 256;
                float v[4]; int jj[4];
                f2unpack(a0[u], v[0], v[2]);
                f2unpack(a1[u], v[1], v[3]);
                jj[0] = pa + j0; jj[1] = pa + j1;
                jj[2] = pa + 256 + j0; jj[3] = pa + 256 + j1;
                int lim = (ta + 1 < n) ? 4 : 2;
#pragma unroll
                for (int q = 0; q < 4; q++) {
                    if (q < lim) {
                        float r = fmaxf(v[q], 0.f);
                        __nv_bfloat16 h = __float2bfloat16(r);
                        g_h1hi[jj[q]] = h;
                        g_h1lo[jj[q]] = __float2bfloat16(r - __bfloat162float(h));
                    }
                }
            }
        }
    }
}

// ============================================================================
// Fused MLP (layers 2,3,4) — unchanged from R14 (passing, 30.2 us)
// ============================================================================
#define SMSTRIDE 136

#define LDSM_X4(r0, r1, r2, r3, addr) \
    asm volatile("ldmatrix.sync.aligned.m8n8.x4.shared.b16 {%0,%1,%2,%3}, [%4];" \
        : "=r"(r0), "=r"(r1), "=r"(r2), "=r"(r3) : "r"(addr))

static __device__ __forceinline__ void mma16816(float* c, const uint32_t* a,
                                                const uint32_t* b) {
    asm volatile(
        "mma.sync.aligned.m16n8k16.row.col.f32.bf16.bf16.f32 "
        "{%0,%1,%2,%3}, {%4,%5,%6,%7}, {%8,%9}, {%0,%1,%2,%3};"
        : "+f"(c[0]), "+f"(c[1]), "+f"(c[2]), "+f"(c[3])
        : "r"(a[0]), "r"(a[1]), "r"(a[2]), "r"(a[3]), "r"(b[0]), "r"(b[1]));
}

static __device__ __forceinline__ void split_pair(__nv_bfloat16* hiA,
                                                  __nv_bfloat16* loA,
                                                  int r, int col,
                                                  float v0, float v1) {
    __nv_bfloat16 h0 = __float2bfloat16(v0), h1 = __float2bfloat16(v1);
    __nv_bfloat16 l0 = __float2bfloat16(v0 - __bfloat162float(h0));
    __nv_bfloat16 l1 = __float2bfloat16(v1 - __bfloat162float(h1));
    __nv_bfloat162 hp, lp;
    hp.x = h0; hp.y = h1; lp.x = l0; lp.y = l1;
    *(__nv_bfloat162*)&hiA[r * SMSTRIDE + col] = hp;
    *(__nv_bfloat162*)&loA[r * SMSTRIDE + col] = lp;
}

template <int KSTEPS>
static __device__ __forceinline__ void mma_loop(uint32_t aHi, uint32_t aLo,
                                                uint32_t bHi, uint32_t bLo,
                                                int m0, int n0, int lane,
                                                float c[2][4][4]) {
    int arow = lane & 15, akhalf = (lane >> 4) << 3;
    int bn = ((lane >> 4) << 3) + (lane & 7), bkhalf = ((lane >> 3) & 1) << 3;
#pragma unroll
    for (int ks = 0; ks < KSTEPS; ks++) {
        int k0 = ks * 16;
        uint32_t ah[2][4], al[2][4], bh[4][2], bl[4][2];
#pragma unroll
        for (int mt = 0; mt < 2; mt++) {
            uint32_t off =
                (uint32_t)(((m0 + mt * 16 + arow) * SMSTRIDE + k0 + akhalf) * 2);
            LDSM_X4(ah[mt][0], ah[mt][1], ah[mt][2], ah[mt][3], aHi + off);
            LDSM_X4(al[mt][0], al[mt][1], al[mt][2], al[mt][3], aLo + off);
        }
#pragma unroll
        for (int ng = 0; ng < 2; ng++) {
            uint32_t off =
                (uint32_t)(((n0 + ng * 16 + bn) * SMSTRIDE + k0 + bkhalf) * 2);
            uint32_t r0, r1, r2, r3;
            LDSM_X4(r0, r1, r2, r3, bHi + off);
            bh[ng * 2][0] = r0;     bh[ng * 2][1] = r1;
            bh[ng * 2 + 1][0] = r2; bh[ng * 2 + 1][1] = r3;
            LDSM_X4(r0, r1, r2, r3, bLo + off);
            bl[ng * 2][0] = r0;     bl[ng * 2][1] = r1;
            bl[ng * 2 + 1][0] = r2; bl[ng * 2 + 1][1] = r3;
        }
#pragma unroll
        for (int mt = 0; mt < 2; mt++)
#pragma unroll
            for (int nt = 0; nt < 4; nt++) {
                mma16816(c[mt][nt], ah[mt], bh[nt]);
                mma16816(c[mt][nt], ah[mt], bl[nt]);
                mma16816(c[mt][nt], al[mt], bh[nt]);
            }
    }
}

#define TILE_A 17408
#define TILE_B 34816
#define OFF_ALO (TILE_A)
#define OFF_BHI (TILE_A * 2)
#define OFF_BLO (TILE_A * 2 + TILE_B)
#define OFF_B2S (TILE_A * 2 + TILE_B * 2)   // 104448
#define OFF_B3S (OFF_B2S + 512)
#define OFF_B4S (OFF_B3S + 512)
#define OFF_OSX (OFF_B4S + 512)
#define SMEM_MLP_BYTES (OFF_OSX + 256)      // 106240

__global__ void __launch_bounds__(256, 2)
k_mlp(const float* __restrict__ b2, const float* __restrict__ b3,
      const float* __restrict__ b4, float* __restrict__ out, int ntok) {
    extern __shared__ __align__(16) char smem[];
    __nv_bfloat16* Ahi = (__nv_bfloat16*)(smem);
    __nv_bfloat16* Alo = (__nv_bfloat16*)(smem + OFF_ALO);
    __nv_bfloat16* Bhi = (__nv_bfloat16*)(smem + OFF_BHI);
    __nv_bfloat16* Blo = (__nv_bfloat16*)(smem + OFF_BLO);
    float* b2s = (float*)(smem + OFF_B2S);
    float* b3s = (float*)(smem + OFF_B3S);
    float* b4s = (float*)(smem + OFF_B4S);
    int*   os  = (int*)(smem + OFF_OSX);
    uint32_t aHi = smem_u32(Ahi), aLo = smem_u32(Alo);
    uint32_t bHi = smem_u32(Bhi), bLo = smem_u32(Blo);

    int tid = threadIdx.x, wid = tid >> 5, lane = tid & 31;
    int m0 = (wid >> 2) * 32, n0 = (wid & 3) * 32;
    int t0 = blockIdx.x * 64;
    if (blockIdx.x == 0 && tid < 20) g_hist[tid] = 0;   // reset for next replay
    if (tid < 128) { b2s[tid] = b2[tid]; b3s[tid] = b3[tid]; b4s[tid] = b4[tid]; }
    if (tid < 64) os[tid] = (t0 + tid < ntok) ? g_order[t0 + tid] : 0;

    float c[2][4][4];
#pragma unroll
    for (int mt = 0; mt < 2; mt++)
#pragma unroll
        for (int nt = 0; nt < 4; nt++)
#pragma unroll
            for (int i = 0; i < 4; i++) c[mt][nt][i] = 0.f;

    for (int ch = 0; ch < 2; ch++) {
        if (ch) __syncthreads();
        for (int p = tid; p < 1024; p += 256) {
            int row = p >> 4, sg = (p & 15) * 8;
            int gt = t0 + row;
            uint4 vh = make_uint4(0, 0, 0, 0), vl = vh;
            if (gt < ntok) {
                size_t src = (size_t)gt * 256 + ch * 128 + sg;
                vh = *(const uint4*)&g_h1hi[src];
                vl = *(const uint4*)&g_h1lo[src];
            }
            *(uint4*)&Ahi[row * SMSTRIDE + sg] = vh;
            *(uint4*)&Alo[row * SMSTRIDE + sg] = vl;
        }
        for (int p = tid; p < 2048; p += 256) {
            int j = p >> 4, sg = (p & 15) * 8;
            size_t src = (size_t)j * 256 + ch * 128 + sg;
            *(uint4*)&Bhi[j * SMSTRIDE + sg] = *(const uint4*)&g_Whi[src];
            *(uint4*)&Blo[j * SMSTRIDE + sg] = *(const uint4*)&g_Wlo[src];
        }
        __syncthreads();
        mma_loop<8>(aHi, aLo, bHi, bLo, m0, n0, lane, c);
    }

#pragma unroll 1
    for (int layer = 0; layer < 2; layer++) {
        size_t wbase = (layer == 0) ? 32768 : 49152;
        const float* bs = (layer == 0) ? b2s : b3s;
        __syncthreads();
#pragma unroll
        for (int mt = 0; mt < 2; mt++)
#pragma unroll
            for (int nt = 0; nt < 4; nt++) {
                int col = n0 + nt * 8 + (lane & 3) * 2;
                int r = m0 + mt * 16 + (lane >> 2);
                float bv0 = bs[col], bv1 = bs[col + 1];
                split_pair(Ahi, Alo, r, col,
                           fmaxf(c[mt][nt][0] + bv0, 0.f),
                           fmaxf(c[mt][nt][1] + bv1, 0.f));
                split_pair(Ahi, Alo, r + 8, col,
                           fmaxf(c[mt][nt][2] + bv0, 0.f),
                           fmaxf(c[mt][nt][3] + bv1, 0.f));
#pragma unroll
                for (int i = 0; i < 4; i++) c[mt][nt][i] = 0.f;
            }
        for (int p = tid; p < 2048; p += 256) {
            int j = p >> 4, sg = (p & 15) * 8;
            size_t src = wbase + (size_t)j * 128 + sg;
            *(uint4*)&Bhi[j * SMSTRIDE + sg] = *(const uint4*)&g_Whi[src];
            *(uint4*)&Blo[j * SMSTRIDE + sg] = *(const uint4*)&g_Wlo[src];
        }
        __syncthreads();
        mma_loop<8>(aHi, aLo, bHi, bLo, m0, n0, lane, c);
    }

#pragma unroll
    for (int mt = 0; mt < 2; mt++)
#pragma unroll
        for (int nt = 0; nt < 4; nt++) {
            int col = n0 + nt * 8 + (lane & 3) * 2;
            int r = m0 + mt * 16 + (lane >> 2);
            float bv0 = b4s[col], bv1 = b4s[col + 1];
            if (t0 + r < ntok) {
                float2 v = make_float2(c[mt][nt][0] + bv0, c[mt][nt][1] + bv1);
                *(float2*)&out[(size_t)os[r] * 128 + col] = v;
            }
            if (t0 + r + 8 < ntok) {
                float2 v = make_float2(c[mt][nt][2] + bv0, c[mt][nt][3] + bv1);
                *(float2*)&out[(size_t)os[r + 8] * 128 + col] = v;
            }
        }
}

// ---------------- launch ----------------------------------------------------
extern "C" void kernel_launch(void* const* d_in, const int* in_sizes, int n_in,
                              void* d_out, int out_size) {
    const int*   seq    = (const int*)  d_in[0];
    const float* xyz    = (const float*)d_in[1];
    const float* dih    = (const float*)d_in[2];
    const int*   cidx   = (const int*)  d_in[3];
    const float* ori    = (const float*)d_in[4];
    /* d_in[5] = atom_mask : unused by reference */
    const float* aa_emb = (const float*)d_in[6];
    const float* ch_emb = (const float*)d_in[7];
    const float* W1 = (const float*)d_in[8];
    const float* b1 = (const float*)d_in[9];
    const float* W2 = (const float*)d_in[10];
    const float* b2 = (const float*)d_in[11];
    const float* W3 = (const float*)d_in[12];
    const float* b3 = (const float*)d_in[13];
    const float* W4 = (const float*)d_in[14];
    const float* b4 = (const float*)d_in[15];
    float* out = (float*)d_out;
    int ntok = in_sizes[0];
    if (ntok > MAXTOK) ntok = MAXTOK;

    int nfeatblk = (ntok + 255) / 256;
    int nblk64 = (ntok + 63) / 64;
    const int SMEM1 = (27344 + 32) * 4;   // 109504 B -> 2 blocks/SM
    cudaFuncSetAttribute(k_l1,  cudaFuncAttributeMaxDynamicSharedMemorySize, SMEM1);
    cudaFuncSetAttribute(k_mlp, cudaFuncAttributeMaxDynamicSharedMemorySize,
                         SMEM_MLP_BYTES);

    k_setup<<<62 + nfeatblk, 256>>>(aa_emb, ch_emb, W1, b1, W2, W3, W4,
                                    xyz, ori, dih, seq, ntok, nfeatblk);
    k_scatter<<<(ntok + 255) / 256, 256>>>(seq, ntok);
    k_l1<<<dim3(20, 7), 512, SMEM1>>>(W1, cidx);
    k_mlp<<<nblk64, 256, SMEM_MLP_BYTES>>>(b2, b3, b4, out, ntok);
}